// round 5
// baseline (speedup 1.0000x reference)
#include <cuda_runtime.h>
#include <cuda_fp16.h>
#include <cstdint>

#define D 64
#define N_NODES_C  20000
#define N_HEDGES_C 400000
#define N_ROWS_TOT (N_NODES_C + N_HEDGES_C)
#define NNZ_TOT    (640000 + 6400000)
#define SCAN_CHUNK 4096
#define NB_MAX     ((N_ROWS_TOT + SCAN_CHUNK - 1) / SCAN_CHUNK)   // 103

// Scratch (allocation-free rule: __device__ globals; zero-initialized at load)
__device__ __half             g_sup1[(size_t)N_NODES_C * D];
__device__ __half             g_sup2[(size_t)N_HEDGES_C * D];
__device__ int                g_cnt[N_ROWS_TOT];    // re-zeroed by spmm_all each run
__device__ int                g_rs[N_ROWS_TOT];
__device__ int                g_cur[N_ROWS_TOT];
__device__ long long          g_fill[NNZ_TOT];
__device__ unsigned long long g_part[NB_MAX];       // lookback; re-zeroed by fill_both

// Side stream + events (static init, outside mem-checkpoint window)
static cudaStream_t g_s2;
static cudaEvent_t  g_evFork, g_evJoin;
struct _StreamInit {
    _StreamInit() {
        cudaStreamCreateWithFlags(&g_s2, cudaStreamNonBlocking);
        cudaEventCreateWithFlags(&g_evFork, cudaEventDisableTiming);
        cudaEventCreateWithFlags(&g_evJoin, cudaEventDisableTiming);
    }
};
static _StreamInit _si;

// ===========================================================================
// GEMM: out[M,64](fp16) = X[M,64] @ W[64,64], fp32 accumulate.
// ===========================================================================
__device__ __forceinline__ void ffma2(unsigned long long& d,
                                      unsigned long long a,
                                      unsigned long long b) {
    asm("fma.rn.f32x2 %0, %1, %2, %0;" : "+l"(d) : "l"(a), "l"(b));
}
__device__ __forceinline__ unsigned long long pack2(float lo, float hi) {
    unsigned long long r;
    asm("mov.b64 %0, {%1, %2};" : "=l"(r) : "f"(lo), "f"(hi));
    return r;
}
__device__ __forceinline__ float2 unpack2(unsigned long long v) {
    float2 r;
    asm("mov.b64 {%0, %1}, %2;" : "=f"(r.x), "=f"(r.y) : "l"(v));
    return r;
}

__global__ void __launch_bounds__(256)
gemm_xw_h(const float* __restrict__ X, const float* __restrict__ W,
          __half* __restrict__ out, int M) {
    __shared__ __align__(16) float Ws[D][D];
    __shared__ __align__(16) float Xs[128][68];
    int t  = threadIdx.x;
    int m0 = blockIdx.x * 128;

    for (int i4 = t; i4 < D * D / 4; i4 += 256)
        *(float4*)&Ws[(i4 * 4) >> 6][(i4 * 4) & 63] = __ldg((const float4*)W + i4);
    for (int i4 = t; i4 < 128 * D / 4; i4 += 256) {
        int r  = i4 >> 4;
        int c4 = (i4 & 15) * 4;
        int row = m0 + r;
        float4 v = (row < M) ? __ldg((const float4*)(X + (size_t)row * D + c4))
                             : make_float4(0.f, 0.f, 0.f, 0.f);
        *(float4*)&Xs[r][c4] = v;
    }
    __syncthreads();

    int rb = (t >> 3) * 4;
    int cg = (t & 7) * 8;

    unsigned long long acc[4][4];
#pragma unroll
    for (int r = 0; r < 4; r++)
#pragma unroll
        for (int j = 0; j < 4; j++) acc[r][j] = pack2(0.f, 0.f);

#pragma unroll
    for (int k = 0; k < D; k++) {
        ulonglong2 w0 = *(const ulonglong2*)&Ws[k][cg];
        ulonglong2 w1 = *(const ulonglong2*)&Ws[k][cg + 4];
#pragma unroll
        for (int r = 0; r < 4; r++) {
            float x = Xs[rb + r][k];
            unsigned long long xx = pack2(x, x);
            ffma2(acc[r][0], xx, w0.x);
            ffma2(acc[r][1], xx, w0.y);
            ffma2(acc[r][2], xx, w1.x);
            ffma2(acc[r][3], xx, w1.y);
        }
    }

#pragma unroll
    for (int r = 0; r < 4; r++) {
        int row = m0 + rb + r;
        if (row < M) {
            __half2 h[4];
#pragma unroll
            for (int j = 0; j < 4; j++) {
                float2 f = unpack2(acc[r][j]);
                h[j] = __float22half2_rn(f);
            }
            *(uint4*)(out + (size_t)row * D + cg) = *(uint4*)h;
        }
    }
}

// ===========================================================================
// Fused histogram over both COO arrays. g_cnt must be zero on entry
// (static init / re-zeroed by spmm_all).
// ===========================================================================
__global__ void hist_both(const int* __restrict__ nrows, const int* __restrict__ hrows,
                          int nnz_n, int nnz_tot, int n_nodes) {
    int i = blockIdx.x * blockDim.x + threadIdx.x;
    if (i >= nnz_tot) return;
    int r = (i < nnz_n) ? __ldcs(&nrows[i]) : n_nodes + __ldcs(&hrows[i - nnz_n]);
    atomicAdd(&g_cnt[r], 1);
}

// ===========================================================================
// Single-kernel exclusive scan (decoupled lookback). 4096 elems/block.
// g_part zero on entry (static init / re-zeroed by fill_both).
// All blocks resident simultaneously (NB_MAX=103 < 148 SMs) -> no deadlock.
// ===========================================================================
__global__ void __launch_bounds__(256) scan_k(int n) {
    __shared__ int sm[256];
    __shared__ int s_exc;
    int b = blockIdx.x, t = threadIdx.x;
    int base = b * SCAN_CHUNK + t * 16;

    int loc[16];
    int s = 0;
#pragma unroll
    for (int k = 0; k < 16; k++) {
        int i = base + k;
        loc[k] = (i < n) ? g_cnt[i] : 0;
        s += loc[k];
    }
    sm[t] = s;
    __syncthreads();
    for (int o = 1; o < 256; o <<= 1) {
        int x = (t >= o) ? sm[t - o] : 0;
        __syncthreads();
        sm[t] += x;
        __syncthreads();
    }
    int thrExc = sm[t] - s;
    int blockTotal = sm[255];

    if (t == 0) {
        if (b == 0) {
            atomicExch(&g_part[0], (2ULL << 32) | (unsigned int)blockTotal);
            s_exc = 0;
        } else {
            atomicExch(&g_part[b], (1ULL << 32) | (unsigned int)blockTotal);
            int exc = 0;
            for (int p = b - 1; p >= 0; p--) {
                unsigned long long w;
                do { w = atomicAdd(&g_part[p], 0ULL); } while ((w >> 32) == 0ULL);
                exc += (int)(unsigned int)w;
                if ((w >> 32) == 2ULL) break;
            }
            atomicExch(&g_part[b], (2ULL << 32) | (unsigned int)(exc + blockTotal));
            s_exc = exc;
        }
    }
    __syncthreads();

    int off = s_exc + thrExc;
    int run = 0;
#pragma unroll
    for (int k = 0; k < 16; k++) {
        int i = base + k;
        if (i < n) {
            g_rs[i]  = off + run;
            g_cur[i] = off + run;
            run += loc[k];
        }
    }
}

// ===========================================================================
// Fused ticketed fill. Also re-zeros the lookback words for the next replay.
// ===========================================================================
__global__ void fill_both(const int* __restrict__ nrows, const int* __restrict__ ncols,
                          const float* __restrict__ nvals,
                          const int* __restrict__ hrows, const int* __restrict__ hcols,
                          const float* __restrict__ hvals,
                          int nnz_n, int nnz_tot, int n_nodes) {
    if (blockIdx.x == 0 && threadIdx.x < NB_MAX) g_part[threadIdx.x] = 0ULL;
    int i = blockIdx.x * blockDim.x + threadIdx.x;
    if (i >= nnz_tot) return;
    int r, c; float v;
    if (i < nnz_n) {
        r = __ldcs(&nrows[i]);
        c = __ldcs(&ncols[i]);
        v = __ldcs(&nvals[i]);
    } else {
        int j = i - nnz_n;
        r = n_nodes + __ldcs(&hrows[j]);
        c = __ldcs(&hcols[j]);
        v = __ldcs(&hvals[j]);
    }
    int pos = atomicAdd(&g_cur[r], 1);
    long long e = ((long long)__float_as_int(v) << 32) | (unsigned int)c;
    __stcs(&g_fill[pos], e);
}

// ===========================================================================
// Fused CSR SpMM, one warp per output row (nodes then hyperedges, output is
// contiguous). Half-warp gather: lanes 0-15 process even entries, 16-31 odd,
// each lane reads 8B of the 128B fp16 dense row -> 2 entries in flight per
// pass; 4-way unroll -> 8 gathers in flight per warp. Cross-half shfl_xor
// reduction, fused relu+bias, one float4 store per low lane.
// Re-zeros g_cnt[row] for the next replay.
// ===========================================================================
__global__ void __launch_bounds__(256)
spmm_all(const float* __restrict__ bias, float* __restrict__ out,
         int n_nodes, int n_rows) {
    __shared__ long long wbuf[8][32];
    int wi = threadIdx.x >> 5;
    int w  = blockIdx.x * 8 + wi;
    if (w >= n_rows) return;
    int lane = threadIdx.x & 31;
    int half = lane >> 4;
    int sub  = lane & 15;

    const __half* tab = (w < n_nodes) ? g_sup1 : g_sup2;

    int start = __ldg(&g_rs[w]);
    int cn    = __ldg(&g_cnt[w]);
    if (lane == 0) g_cnt[w] = 0;          // clean state for next replay

    float4 A0 = {0.f,0.f,0.f,0.f}, A1 = A0, A2 = A0, A3 = A0;

    for (int bb = 0; bb < cn; bb += 32) {
        int m = min(cn - bb, 32);
        if (lane < m) wbuf[wi][lane] = __ldcs(&g_fill[start + bb + lane]);
        __syncwarp();
        int j = half;                      // half 0: even entries, half 1: odd
        for (; j + 6 < m; j += 8) {
            long long e0 = wbuf[wi][j];
            long long e1 = wbuf[wi][j + 2];
            long long e2 = wbuf[wi][j + 4];
            long long e3 = wbuf[wi][j + 6];
            uint2 p0 = __ldg((const uint2*)(tab + (size_t)(unsigned int)(e0 & 0xffffffffu) * D) + sub);
            uint2 p1 = __ldg((const uint2*)(tab + (size_t)(unsigned int)(e1 & 0xffffffffu) * D) + sub);
            uint2 p2 = __ldg((const uint2*)(tab + (size_t)(unsigned int)(e2 & 0xffffffffu) * D) + sub);
            uint2 p3 = __ldg((const uint2*)(tab + (size_t)(unsigned int)(e3 & 0xffffffffu) * D) + sub);
            float v0 = __int_as_float((int)(e0 >> 32));
            float v1 = __int_as_float((int)(e1 >> 32));
            float v2 = __int_as_float((int)(e2 >> 32));
            float v3 = __int_as_float((int)(e3 >> 32));
            float2 f0a = __half22float2(*(__half2*)&p0.x), f0b = __half22float2(*(__half2*)&p0.y);
            float2 f1a = __half22float2(*(__half2*)&p1.x), f1b = __half22float2(*(__half2*)&p1.y);
            float2 f2a = __half22float2(*(__half2*)&p2.x), f2b = __half22float2(*(__half2*)&p2.y);
            float2 f3a = __half22float2(*(__half2*)&p3.x), f3b = __half22float2(*(__half2*)&p3.y);
            A0.x += v0 * f0a.x; A0.y += v0 * f0a.y; A0.z += v0 * f0b.x; A0.w += v0 * f0b.y;
            A1.x += v1 * f1a.x; A1.y += v1 * f1a.y; A1.z += v1 * f1b.x; A1.w += v1 * f1b.y;
            A2.x += v2 * f2a.x; A2.y += v2 * f2a.y; A2.z += v2 * f2b.x; A2.w += v2 * f2b.y;
            A3.x += v3 * f3a.x; A3.y += v3 * f3a.y; A3.z += v3 * f3b.x; A3.w += v3 * f3b.y;
        }
        for (; j < m; j += 2) {
            long long e0 = wbuf[wi][j];
            uint2 p0 = __ldg((const uint2*)(tab + (size_t)(unsigned int)(e0 & 0xffffffffu) * D) + sub);
            float v0 = __int_as_float((int)(e0 >> 32));
            float2 f0a = __half22float2(*(__half2*)&p0.x), f0b = __half22float2(*(__half2*)&p0.y);
            A0.x += v0 * f0a.x; A0.y += v0 * f0a.y; A0.z += v0 * f0b.x; A0.w += v0 * f0b.y;
        }
        __syncwarp();
    }

    float4 A;
    A.x = (A0.x + A1.x) + (A2.x + A3.x);
    A.y = (A0.y + A1.y) + (A2.y + A3.y);
    A.z = (A0.z + A1.z) + (A2.z + A3.z);
    A.w = (A0.w + A1.w) + (A2.w + A3.w);
    A.x += __shfl_xor_sync(0xffffffffu, A.x, 16);
    A.y += __shfl_xor_sync(0xffffffffu, A.y, 16);
    A.z += __shfl_xor_sync(0xffffffffu, A.z, 16);
    A.w += __shfl_xor_sync(0xffffffffu, A.w, 16);

    if (half == 0) {
        float4 bs = __ldg((const float4*)bias + sub);
        float4 o;
        o.x = fmaxf(A.x, 0.f) + bs.x;
        o.y = fmaxf(A.y, 0.f) + bs.y;
        o.z = fmaxf(A.z, 0.f) + bs.z;
        o.w = fmaxf(A.w, 0.f) + bs.w;
        ((float4*)(out + (size_t)w * D))[sub] = o;
    }
}

// ===========================================================================
extern "C" void kernel_launch(void* const* d_in, const int* in_sizes, int n_in,
                              void* d_out, int out_size) {
    const float* node_x = (const float*)d_in[0];
    const float* he_x   = (const float*)d_in[1];
    const int*   nrows  = (const int*)  d_in[2];
    const int*   ncols  = (const int*)  d_in[3];
    const float* nvals  = (const float*)d_in[4];
    const int*   hrows  = (const int*)  d_in[5];
    const int*   hcols  = (const int*)  d_in[6];
    const float* hvals  = (const float*)d_in[7];
    const float* W      = (const float*)d_in[8];
    const float* bias   = (const float*)d_in[9];

    int n_nodes = in_sizes[0] / D;
    int n_he    = in_sizes[1] / D;
    int nnz_n   = in_sizes[2];
    int nnz_h   = in_sizes[5];
    int n_rows  = n_nodes + n_he;
    int nnz_tot = nnz_n + nnz_h;
    int nb      = (n_rows + SCAN_CHUNK - 1) / SCAN_CHUNK;

    float* out = (float*)d_out;

    __half* sup1; __half* sup2;
    cudaGetSymbolAddress((void**)&sup1, g_sup1);
    cudaGetSymbolAddress((void**)&sup2, g_sup2);

    // Fork: GEMMs on side stream, CSR build on main stream (independent)
    cudaEventRecord(g_evFork, 0);
    cudaStreamWaitEvent(g_s2, g_evFork, 0);
    gemm_xw_h<<<(n_nodes + 127) / 128, 256, 0, g_s2>>>(node_x, W, sup1, n_nodes);
    gemm_xw_h<<<(n_he    + 127) / 128, 256, 0, g_s2>>>(he_x,   W, sup2, n_he);
    cudaEventRecord(g_evJoin, g_s2);

    hist_both<<<(nnz_tot + 255) / 256, 256>>>(nrows, hrows, nnz_n, nnz_tot, n_nodes);
    scan_k<<<nb, 256>>>(n_rows);
    fill_both<<<(nnz_tot + 255) / 256, 256>>>(nrows, ncols, nvals,
                                              hrows, hcols, hvals,
                                              nnz_n, nnz_tot, n_nodes);

    cudaStreamWaitEvent(0, g_evJoin, 0);
    spmm_all<<<(n_rows + 7) / 8, 256>>>(bias, out, n_nodes, n_rows);
}

// round 6
// speedup vs baseline: 2.0466x; 2.0466x over previous
#include <cuda_runtime.h>
#include <cuda_fp16.h>
#include <cstdint>

#define D 64
#define N_NODES_C  20000
#define N_HEDGES_C 400000
#define N_ROWS_TOT (N_NODES_C + N_HEDGES_C)
#define NNZ_TOT    (640000 + 6400000)

// Scratch (allocation-free rule: __device__ globals)
__device__ __half    g_sup1[(size_t)N_NODES_C * D];
__device__ __half    g_sup2[(size_t)N_HEDGES_C * D];
__device__ int       g_cnt[N_ROWS_TOT];
__device__ int       g_rs[N_ROWS_TOT];
__device__ int       g_cur[N_ROWS_TOT];
__device__ long long g_fill[NNZ_TOT];
__device__ int       g_bsums[256];

// ===========================================================================
// GEMM: out[M,64](fp16) = X[M,64] @ W[64,64], fp32 accumulate.
// ===========================================================================
__device__ __forceinline__ void ffma2(unsigned long long& d,
                                      unsigned long long a,
                                      unsigned long long b) {
    asm("fma.rn.f32x2 %0, %1, %2, %0;" : "+l"(d) : "l"(a), "l"(b));
}
__device__ __forceinline__ unsigned long long pack2(float lo, float hi) {
    unsigned long long r;
    asm("mov.b64 %0, {%1, %2};" : "=l"(r) : "f"(lo), "f"(hi));
    return r;
}
__device__ __forceinline__ float2 unpack2(unsigned long long v) {
    float2 r;
    asm("mov.b64 {%0, %1}, %2;" : "=f"(r.x), "=f"(r.y) : "l"(v));
    return r;
}

__global__ void __launch_bounds__(256)
gemm_xw_h(const float* __restrict__ X, const float* __restrict__ W,
          __half* __restrict__ out, int M) {
    __shared__ __align__(16) float Ws[D][D];
    __shared__ __align__(16) float Xs[128][68];
    int t  = threadIdx.x;
    int m0 = blockIdx.x * 128;

    for (int i4 = t; i4 < D * D / 4; i4 += 256)
        *(float4*)&Ws[(i4 * 4) >> 6][(i4 * 4) & 63] = __ldg((const float4*)W + i4);
    for (int i4 = t; i4 < 128 * D / 4; i4 += 256) {
        int r  = i4 >> 4;
        int c4 = (i4 & 15) * 4;
        int row = m0 + r;
        float4 v = (row < M) ? __ldg((const float4*)(X + (size_t)row * D + c4))
                             : make_float4(0.f, 0.f, 0.f, 0.f);
        *(float4*)&Xs[r][c4] = v;
    }
    __syncthreads();

    int rb = (t >> 3) * 4;
    int cg = (t & 7) * 8;

    unsigned long long acc[4][4];
#pragma unroll
    for (int r = 0; r < 4; r++)
#pragma unroll
        for (int j = 0; j < 4; j++) acc[r][j] = pack2(0.f, 0.f);

#pragma unroll
    for (int k = 0; k < D; k++) {
        ulonglong2 w0 = *(const ulonglong2*)&Ws[k][cg];
        ulonglong2 w1 = *(const ulonglong2*)&Ws[k][cg + 4];
#pragma unroll
        for (int r = 0; r < 4; r++) {
            float x = Xs[rb + r][k];
            unsigned long long xx = pack2(x, x);
            ffma2(acc[r][0], xx, w0.x);
            ffma2(acc[r][1], xx, w0.y);
            ffma2(acc[r][2], xx, w1.x);
            ffma2(acc[r][3], xx, w1.y);
        }
    }

#pragma unroll
    for (int r = 0; r < 4; r++) {
        int row = m0 + rb + r;
        if (row < M) {
            __half2 h[4];
#pragma unroll
            for (int j = 0; j < 4; j++) {
                float2 f = unpack2(acc[r][j]);
                h[j] = __float22half2_rn(f);
            }
            *(uint4*)(out + (size_t)row * D + cg) = *(uint4*)h;
        }
    }
}

// ===========================================================================
// CSR build: histogram -> 3-phase exclusive scan -> ticketed fill  (R3-proven)
// ===========================================================================
__global__ void hist_k(const int* __restrict__ rows, int nnz, int base) {
    int i = blockIdx.x * blockDim.x + threadIdx.x;
    if (i < nnz) atomicAdd(&g_cnt[base + __ldcs(&rows[i])], 1);
}

__global__ void __launch_bounds__(256) scanA_k(int n) {
    __shared__ int sm[256];
    int b = blockIdx.x, t = threadIdx.x;
    int base = b * 4096 + t * 16;
    int s = 0;
#pragma unroll
    for (int k = 0; k < 16; k++) {
        int i = base + k;
        if (i < n) s += g_cnt[i];
    }
    sm[t] = s;
    __syncthreads();
    for (int o = 128; o > 0; o >>= 1) {
        if (t < o) sm[t] += sm[t + o];
        __syncthreads();
    }
    if (t == 0) g_bsums[b] = sm[0];
}

__global__ void __launch_bounds__(256) scanB_k(int nb) {
    __shared__ int sm[256];
    int t = threadIdx.x;
    int v = (t < nb) ? g_bsums[t] : 0;
    sm[t] = v;
    __syncthreads();
    for (int o = 1; o < 256; o <<= 1) {
        int x = (t >= o) ? sm[t - o] : 0;
        __syncthreads();
        sm[t] += x;
        __syncthreads();
    }
    if (t < nb) g_bsums[t] = sm[t] - v;
}

__global__ void __launch_bounds__(256) scanC_k(int n) {
    __shared__ int sm[256];
    int b = blockIdx.x, t = threadIdx.x;
    int base = b * 4096 + t * 16;
    int loc[16];
    int s = 0;
#pragma unroll
    for (int k = 0; k < 16; k++) {
        int i = base + k;
        loc[k] = (i < n) ? g_cnt[i] : 0;
        s += loc[k];
    }
    sm[t] = s;
    __syncthreads();
    for (int o = 1; o < 256; o <<= 1) {
        int x = (t >= o) ? sm[t - o] : 0;
        __syncthreads();
        sm[t] += x;
        __syncthreads();
    }
    int off = g_bsums[b] + sm[t] - s;
    int run = 0;
#pragma unroll
    for (int k = 0; k < 16; k++) {
        int i = base + k;
        if (i < n) {
            g_rs[i]  = off + run;
            g_cur[i] = off + run;
            run += loc[k];
        }
    }
}

__global__ void fill_k(const int* __restrict__ rows, const int* __restrict__ cols,
                       const float* __restrict__ vals, int nnz, int base) {
    int i = blockIdx.x * blockDim.x + threadIdx.x;
    if (i >= nnz) return;
    int r   = base + __ldcs(&rows[i]);
    int pos = atomicAdd(&g_cur[r], 1);
    long long e = ((long long)__float_as_int(__ldcs(&vals[i])) << 32)
                | (unsigned int)__ldcs(&cols[i]);
    g_fill[pos] = e;
}

// ===========================================================================
// CSR SpMM: ONE WARP = FOUR ROWS. Lane groups of 8 batch-load each row's fill
// entries into smem; inner loop issues 4 independent 128B gathers per step
// (one per row), unrolled x8 -> ~16-32 loads in flight per warp. Tail entries
// padded with (c=0, v=0): padded gathers all hit one L1-hot line. Fused
// relu+bias; one float2 store per lane per row.
// ===========================================================================
__global__ void __launch_bounds__(256)
spmm_csr4(const __half* __restrict__ dense, const float* __restrict__ bias,
          float* __restrict__ out, int row_base, int nrows) {
    __shared__ long long wbuf[8][32];
    int wi   = threadIdx.x >> 5;
    int lane = threadIdx.x & 31;
    int r0   = (blockIdx.x * 8 + wi) * 4;
    if (r0 >= nrows) return;
    int sub  = lane & 7;     // entry slot within my row's 8-entry batch
    int rsel = lane >> 3;    // which of the 4 rows this lane loads fill for

    int myrow = r0 + rsel;
    bool rv   = (myrow < nrows);
    int start = rv ? __ldg(&g_rs[row_base + myrow]) : 0;
    int cn    = rv ? __ldg(&g_cnt[row_base + myrow]) : 0;

    int cn0 = __shfl_sync(0xffffffffu, cn, 0);
    int cn1 = __shfl_sync(0xffffffffu, cn, 8);
    int cn2 = __shfl_sync(0xffffffffu, cn, 16);
    int cn3 = __shfl_sync(0xffffffffu, cn, 24);
    int cmax = max(max(cn0, cn1), max(cn2, cn3));

    float2 a0 = {0.f, 0.f}, a1 = a0, a2 = a0, a3 = a0;

    for (int bb = 0; bb < cmax; bb += 8) {
        wbuf[wi][lane] = (bb + sub < cn) ? __ldcs(&g_fill[start + bb + sub]) : 0LL;
        __syncwarp();
#pragma unroll
        for (int j = 0; j < 8; j++) {
            long long e0 = wbuf[wi][j];
            long long e1 = wbuf[wi][8 + j];
            long long e2 = wbuf[wi][16 + j];
            long long e3 = wbuf[wi][24 + j];
            __half2 h0 = __ldg((const __half2*)(dense + (size_t)(unsigned int)e0 * D) + lane);
            __half2 h1 = __ldg((const __half2*)(dense + (size_t)(unsigned int)e1 * D) + lane);
            __half2 h2 = __ldg((const __half2*)(dense + (size_t)(unsigned int)e2 * D) + lane);
            __half2 h3 = __ldg((const __half2*)(dense + (size_t)(unsigned int)e3 * D) + lane);
            float v0 = __int_as_float((int)(e0 >> 32));
            float v1 = __int_as_float((int)(e1 >> 32));
            float v2 = __int_as_float((int)(e2 >> 32));
            float v3 = __int_as_float((int)(e3 >> 32));
            float2 f0 = __half22float2(h0);
            float2 f1 = __half22float2(h1);
            float2 f2 = __half22float2(h2);
            float2 f3 = __half22float2(h3);
            a0.x += v0 * f0.x; a0.y += v0 * f0.y;
            a1.x += v1 * f1.x; a1.y += v1 * f1.y;
            a2.x += v2 * f2.x; a2.y += v2 * f2.y;
            a3.x += v3 * f3.x; a3.y += v3 * f3.y;
        }
        __syncwarp();
    }

    float2 bs = __ldg((const float2*)bias + lane);
    {
        float2 o; o.x = fmaxf(a0.x, 0.f) + bs.x; o.y = fmaxf(a0.y, 0.f) + bs.y;
        ((float2*)(out + (size_t)r0 * D))[lane] = o;
    }
    if (r0 + 1 < nrows) {
        float2 o; o.x = fmaxf(a1.x, 0.f) + bs.x; o.y = fmaxf(a1.y, 0.f) + bs.y;
        ((float2*)(out + (size_t)(r0 + 1) * D))[lane] = o;
    }
    if (r0 + 2 < nrows) {
        float2 o; o.x = fmaxf(a2.x, 0.f) + bs.x; o.y = fmaxf(a2.y, 0.f) + bs.y;
        ((float2*)(out + (size_t)(r0 + 2) * D))[lane] = o;
    }
    if (r0 + 3 < nrows) {
        float2 o; o.x = fmaxf(a3.x, 0.f) + bs.x; o.y = fmaxf(a3.y, 0.f) + bs.y;
        ((float2*)(out + (size_t)(r0 + 3) * D))[lane] = o;
    }
}

// ===========================================================================
extern "C" void kernel_launch(void* const* d_in, const int* in_sizes, int n_in,
                              void* d_out, int out_size) {
    const float* node_x = (const float*)d_in[0];
    const float* he_x   = (const float*)d_in[1];
    const int*   nrows  = (const int*)  d_in[2];
    const int*   ncols  = (const int*)  d_in[3];
    const float* nvals  = (const float*)d_in[4];
    const int*   hrows  = (const int*)  d_in[5];
    const int*   hcols  = (const int*)  d_in[6];
    const float* hvals  = (const float*)d_in[7];
    const float* W      = (const float*)d_in[8];
    const float* bias   = (const float*)d_in[9];

    int n_nodes = in_sizes[0] / D;
    int n_he    = in_sizes[1] / D;
    int nnz_n   = in_sizes[2];
    int nnz_h   = in_sizes[5];
    int n_rows  = n_nodes + n_he;
    int nb      = (n_rows + 4095) / 4096;

    float* out1 = (float*)d_out;
    float* out2 = out1 + (size_t)n_nodes * D;

    __half* sup1; __half* sup2; int* cnt;
    cudaGetSymbolAddress((void**)&sup1, g_sup1);
    cudaGetSymbolAddress((void**)&sup2, g_sup2);
    cudaGetSymbolAddress((void**)&cnt,  g_cnt);

    // --- CSR build ---
    cudaMemsetAsync(cnt, 0, (size_t)n_rows * sizeof(int), 0);
    hist_k<<<(nnz_n + 255) / 256, 256>>>(nrows, nnz_n, 0);
    hist_k<<<(nnz_h + 255) / 256, 256>>>(hrows, nnz_h, n_nodes);
    scanA_k<<<nb, 256>>>(n_rows);
    scanB_k<<<1, 256>>>(nb);
    scanC_k<<<nb, 256>>>(n_rows);
    fill_k<<<(nnz_n + 255) / 256, 256>>>(nrows, ncols, nvals, nnz_n, 0);
    fill_k<<<(nnz_h + 255) / 256, 256>>>(hrows, hcols, hvals, nnz_h, n_nodes);

    // --- dense GEMMs ---
    gemm_xw_h<<<(n_nodes + 127) / 128, 256>>>(node_x, W, sup1, n_nodes);
    gemm_xw_h<<<(n_he    + 127) / 128, 256>>>(he_x,   W, sup2, n_he);

    // --- CSR SpMM: 4 rows per warp, 32 rows per block ---
    spmm_csr4<<<(n_nodes + 31) / 32, 256>>>(sup1, bias, out1, 0,       n_nodes);
    spmm_csr4<<<(n_he    + 31) / 32, 256>>>(sup2, bias, out2, n_nodes, n_he);
}